// round 9
// baseline (speedup 1.0000x reference)
#include <cuda_runtime.h>
#include <cstdint>

// TaylorExp, 4 rows/warp compute (R8 algebra), block output staged in smem,
// drained by one cp.async.bulk (TMA) store per block.
// Per row: p[0]=1, p[1+i]=2*s_quad*x[i]; q_ext[j]=x[j mod 16]/2.
// out[m] = p[t>>4]*q[t&15], t=m-1 (m>=1); out[0]=1.
// Block = 32 rows = 8736 floats = 34944 B (16B-multiple, gmem base aligned).

#define D 16
#define OPR 273
#define THREADS 256
#define ROWS_PER_BLOCK 32
#define RS 56
#define OUT_WORDS (ROWS_PER_BLOCK * OPR)   // 8736 floats = 34944 B

__device__ __forceinline__ uint32_t smem_u32(const void* p) {
    return (uint32_t)__cvta_generic_to_shared(p);
}

__global__ __launch_bounds__(THREADS)
void taylor_tma_kernel(const float* __restrict__ x,
                       float* __restrict__ out,
                       int rows)
{
    __shared__ __align__(16) float sm[ROWS_PER_BLOCK * RS];   // p/q staging
    __shared__ __align__(16) float os[OUT_WORDS];             // output staging

    const int tid = threadIdx.x;
    const int row0 = blockIdx.x * ROWS_PER_BLOCK;

    if (row0 + ROWS_PER_BLOCK <= rows) {
        // ---- stage pp2/q for 32 rows (coalesced 512B x load) ----
        if (tid < 128) {
            const int lr = tid >> 2;                 // local row 0..31
            const int jb = (tid & 3) << 2;           // j base 0,4,8,12
            const float4 f = *reinterpret_cast<const float4*>(
                x + (size_t)(row0 + lr) * D + jb);
            const int rb = lr * RS;
            const int qb = rb + 34 + (((lr & 3) + 3) & 3);
            const float ps = 0.35355339059327378f;   // 2*s_quad
            const float v0 = f.x * ps, v1 = f.y * ps;
            const float v2 = f.z * ps, v3 = f.w * ps;
            sm[rb + 2 * (jb + 1)] = v0; sm[rb + 2 * (jb + 1) - 1] = v0;
            sm[rb + 2 * (jb + 2)] = v1; sm[rb + 2 * (jb + 2) - 1] = v1;
            sm[rb + 2 * (jb + 3)] = v2; sm[rb + 2 * (jb + 3) - 1] = v2;
            sm[rb + 2 * (jb + 4)] = v3; sm[rb + 2 * (jb + 4) - 1] = v3;
            sm[qb + jb + 0] = f.x * 0.5f;
            sm[qb + jb + 1] = f.y * 0.5f;
            sm[qb + jb + 2] = f.z * 0.5f;
            sm[qb + jb + 3] = f.w * 0.5f;
            if (jb == 0) {
                sm[rb] = 1.0f;                       // pp2[0].x = p[0]
                sm[qb + 16] = f.x * 0.5f;            // wrap replicas
                sm[qb + 17] = f.y * 0.5f;
                sm[qb + 18] = f.z * 0.5f;
            }
            if (jb == 12) sm[rb + 33] = v3;          // pp2[16].y pad
        }
        __syncthreads();

        const int warp = tid >> 5;
        const int lane = tid & 31;
        const int l4 = lane << 2;
        const int wb = warp * (4 * RS);

        const int rb0 = wb,        rb1 = wb + RS;
        const int rb2 = wb + 2*RS, rb3 = wb + 3*RS;
        const int qb0 = rb0 + 37, qb1 = rb1 + 34;
        const int qb2 = rb2 + 35, qb3 = rb3 + 36;

        // row-constant q4 vectors (hoisted; b0_rl = (4*(lane&3)+15-rl)&15)
        const int a3 = (lane & 3) << 2;
        const float4 q40 = *reinterpret_cast<const float4*>(&sm[qb0 + ((a3 + 15) & 15)]);
        const float4 q41 = *reinterpret_cast<const float4*>(&sm[qb1 + ((a3 + 14) & 15)]);
        const float4 q42 = *reinterpret_cast<const float4*>(&sm[qb2 + ((a3 + 13) & 15)]);
        const float4 q43 = *reinterpret_cast<const float4*>(&sm[qb3 + ((a3 + 12) & 15)]);

        // output staged in smem: 273 float4 per warp group
        float4* __restrict__ ob = reinterpret_cast<float4*>(os) + warp * 273 + lane;

#define BODY(RB, T0, T0A, Q4, V)                                            \
        {                                                                   \
            const int t0_ = (T0);                                           \
            const int b0_ = t0_ & 15;                                       \
            const int a0_ = (T0A) >> 4;                                     \
            const float2 pq_ =                                              \
                *reinterpret_cast<const float2*>(&sm[(RB) + 2 * a0_]);      \
            V.x = pq_.x * (Q4).x;                                           \
            V.y = (b0_ >= 15 ? pq_.y : pq_.x) * (Q4).y;                     \
            V.z = (b0_ >= 14 ? pq_.y : pq_.x) * (Q4).z;                     \
            V.w = (b0_ >= 13 ? pq_.y : pq_.x) * (Q4).w;                     \
        }
#define SEL4(C, A, B) make_float4((C)?(A).x:(B).x, (C)?(A).y:(B).y, \
                                  (C)?(A).z:(B).z, (C)?(A).w:(B).w)

        float4 v;

        // s=0: row0, C=-1; lane0 fixup from q40 registers.
        BODY(rb0, l4 - 1, (l4 - 1) < 0 ? 0 : (l4 - 1), q40, v);
        if (lane == 0) { v.x = 1.0f; v.y = q40.y; v.z = q40.z; v.w = q40.w; }
        ob[0] = v;

        // s=1: row0, C=127.
        BODY(rb0, l4 + 127, l4 + 127, q40, v);
        ob[32] = v;

        // s=2: lanes<=4 row0 (C=255), lanes>=5 row1 (C=-18); lane4 mixed.
        {
            const bool hi = lane >= 5;
            const int t0 = l4 + (hi ? -18 : 255);
            const float4 q4m = SEL4(hi, q41, q40);
            BODY(hi ? rb1 : rb0, t0, t0, q4m, v);
            if (lane == 4) { v.y = 1.0f; v.z = sm[qb1]; v.w = sm[qb1 + 1]; }
            ob[64] = v;
        }

        // s=3: row1, C=110.
        BODY(rb1, l4 + 110, l4 + 110, q41, v);
        ob[96] = v;

        // s=4: lanes<=8 row1 (C=238), lanes>=9 row2 (C=-35); lane8 mixed.
        {
            const bool hi = lane >= 9;
            const int t0 = l4 + (hi ? -35 : 238);
            const float4 q4m = SEL4(hi, q42, q41);
            BODY(hi ? rb2 : rb1, t0, t0, q4m, v);
            if (lane == 8) { v.z = 1.0f; v.w = q42.w; }   // q2[0] = q42.w (b0=13)
            ob[128] = v;
        }

        // s=5: row2, C=93.
        BODY(rb2, l4 + 93, l4 + 93, q42, v);
        ob[160] = v;

        // s=6: lanes<=12 row2 (C=221), lanes>=13 row3 (C=-52); lane12 mixed.
        {
            const bool hi = lane >= 13;
            const int t0 = l4 + (hi ? -52 : 221);
            const float4 q4m = SEL4(hi, q43, q42);
            BODY(hi ? rb3 : rb2, t0, t0, q4m, v);
            if (lane == 12) { v.w = 1.0f; }
            ob[192] = v;
        }

        // s=7: row3, C=76.
        BODY(rb3, l4 + 76, l4 + 76, q43, v);
        ob[224] = v;

        // s=8: row3, C=204, lanes 0..16 only.
        if (lane < 17) {
            BODY(rb3, l4 + 204, l4 + 204, q43, v);
            ob[256] = v;
        }
#undef BODY
#undef SEL4

        // ---- drain: one TMA bulk store for the whole block ----
        __syncthreads();
        if (tid == 0) {
            asm volatile("fence.proxy.async.shared::cta;" ::: "memory");
            float* gdst = out + (size_t)row0 * OPR;     // 34944B-aligned offset
            const uint32_t ssrc = smem_u32(os);
            asm volatile(
                "cp.async.bulk.global.shared::cta.bulk_group [%0], [%1], %2;"
                :: "l"(gdst), "r"(ssrc), "r"((uint32_t)(OUT_WORDS * 4))
                : "memory");
            asm volatile("cp.async.bulk.commit_group;" ::: "memory");
            asm volatile("cp.async.bulk.wait_group 0;" ::: "memory");
        }
    } else {
        // partial tail block (not hit for the bench shape): scalar fallback
        const float s_quad = 0.17677669529663689f;
        const unsigned int iend = (unsigned int)rows * OPR;
        for (unsigned int g = (unsigned int)row0 * OPR + tid; g < iend;
             g += THREADS) {
            const unsigned int row = g / OPR;
            const int mm = (int)(g - row * OPR);
            const float* xr = x + (size_t)row * D;
            float vv;
            if (mm == 0) vv = 1.0f;
            else if (mm < 17) vv = xr[mm - 1] * 0.5f;
            else { const int k = mm - 17; vv = xr[k >> 4] * xr[k & 15] * s_quad; }
            out[g] = vv;
        }
    }
}

extern "C" void kernel_launch(void* const* d_in, const int* in_sizes, int n_in,
                              void* d_out, int out_size) {
    const float* x = (const float*)d_in[0];
    float* out = (float*)d_out;

    const int rows = in_sizes[0] / D;                            // 262144
    const int blocks = (rows + ROWS_PER_BLOCK - 1) / ROWS_PER_BLOCK; // 8192

    taylor_tma_kernel<<<blocks, THREADS>>>(x, out, rows);
}

// round 10
// speedup vs baseline: 1.1750x; 1.1750x over previous
#include <cuda_runtime.h>
#include <cstdint>

// TaylorExp, 4 rows/warp, unrolled sweeps, row-hoisted q4 registers + fused
// p-pair LDS.64 (R8 structure) + streaming (evict-first) output stores.
// Per row: p[0]=1, p[1+i]=2*s_quad*x[i]; q_ext[j]=x[j mod 16]/2 (j=0..18).
// out[m] = p[t>>4]*q[t&15], t=m-1 (m>=1); out[0]=1.

#define D 16
#define OPR 273
#define THREADS 256
#define ROWS_PER_BLOCK 32
#define RS 56

__device__ __forceinline__ void stcs4(float4* p, float4 v) {
#if __CUDA_ARCH__ >= 800
    __stcs(p, v);            // st.global.cs.v4 — evict-first streaming store
#else
    *p = v;
#endif
}

__global__ __launch_bounds__(THREADS)
void taylor_hqs_kernel(const float* __restrict__ x,
                       float* __restrict__ out,
                       int rows)
{
    __shared__ __align__(16) float sm[(THREADS / 32) * 4 * RS]; // 1792 floats

    const int tid = threadIdx.x;
    const int row0 = blockIdx.x * ROWS_PER_BLOCK;

    if (row0 + ROWS_PER_BLOCK <= rows) {
        // ---- stage pp2/q for 32 rows (coalesced 512B x load) ----
        if (tid < 128) {
            const int lr = tid >> 2;                 // local row 0..31
            const int jb = (tid & 3) << 2;           // j base 0,4,8,12
            const float4 f = __ldg(reinterpret_cast<const float4*>(
                x + (size_t)(row0 + lr) * D + jb));
            const int rb = lr * RS;
            const int qb = rb + 34 + (((lr & 3) + 3) & 3);
            const float ps = 0.35355339059327378f;   // 2*s_quad
            const float v0 = f.x * ps, v1 = f.y * ps;
            const float v2 = f.z * ps, v3 = f.w * ps;
            sm[rb + 2 * (jb + 1)] = v0; sm[rb + 2 * (jb + 1) - 1] = v0;
            sm[rb + 2 * (jb + 2)] = v1; sm[rb + 2 * (jb + 2) - 1] = v1;
            sm[rb + 2 * (jb + 3)] = v2; sm[rb + 2 * (jb + 3) - 1] = v2;
            sm[rb + 2 * (jb + 4)] = v3; sm[rb + 2 * (jb + 4) - 1] = v3;
            sm[qb + jb + 0] = f.x * 0.5f;
            sm[qb + jb + 1] = f.y * 0.5f;
            sm[qb + jb + 2] = f.z * 0.5f;
            sm[qb + jb + 3] = f.w * 0.5f;
            if (jb == 0) {
                sm[rb] = 1.0f;                       // pp2[0].x = p[0]
                sm[qb + 16] = f.x * 0.5f;            // wrap replicas
                sm[qb + 17] = f.y * 0.5f;
                sm[qb + 18] = f.z * 0.5f;
            }
            if (jb == 12) sm[rb + 33] = v3;          // pp2[16].y pad
        }
        __syncthreads();

        const int warp = tid >> 5;
        const int lane = tid & 31;
        const int l4 = lane << 2;
        const int wb = warp * (4 * RS);

        const int rb0 = wb,        rb1 = wb + RS;
        const int rb2 = wb + 2*RS, rb3 = wb + 3*RS;
        const int qb0 = rb0 + 37, qb1 = rb1 + 34;
        const int qb2 = rb2 + 35, qb3 = rb3 + 36;

        // row-constant q4 vectors (hoisted; b0_rl = (4*(lane&3)+15-rl)&15)
        const int a3 = (lane & 3) << 2;
        const float4 q40 = *reinterpret_cast<const float4*>(&sm[qb0 + ((a3 + 15) & 15)]);
        const float4 q41 = *reinterpret_cast<const float4*>(&sm[qb1 + ((a3 + 14) & 15)]);
        const float4 q42 = *reinterpret_cast<const float4*>(&sm[qb2 + ((a3 + 13) & 15)]);
        const float4 q43 = *reinterpret_cast<const float4*>(&sm[qb3 + ((a3 + 12) & 15)]);

        float4* __restrict__ ob = reinterpret_cast<float4*>(
            out + (size_t)(row0 + warp * 4) * OPR) + lane;

#define BODY(RB, T0, T0A, Q4, V)                                            \
        {                                                                   \
            const int t0_ = (T0);                                           \
            const int b0_ = t0_ & 15;                                       \
            const int a0_ = (T0A) >> 4;                                     \
            const float2 pq_ =                                              \
                *reinterpret_cast<const float2*>(&sm[(RB) + 2 * a0_]);      \
            V.x = pq_.x * (Q4).x;                                           \
            V.y = (b0_ >= 15 ? pq_.y : pq_.x) * (Q4).y;                     \
            V.z = (b0_ >= 14 ? pq_.y : pq_.x) * (Q4).z;                     \
            V.w = (b0_ >= 13 ? pq_.y : pq_.x) * (Q4).w;                     \
        }
#define SEL4(C, A, B) make_float4((C)?(A).x:(B).x, (C)?(A).y:(B).y, \
                                  (C)?(A).z:(B).z, (C)?(A).w:(B).w)

        float4 v;

        // s=0: row0, C=-1; lane0 fixup from q40 registers.
        BODY(rb0, l4 - 1, (l4 - 1) < 0 ? 0 : (l4 - 1), q40, v);
        if (lane == 0) { v.x = 1.0f; v.y = q40.y; v.z = q40.z; v.w = q40.w; }
        stcs4(&ob[0], v);

        // s=1: row0, C=127.
        BODY(rb0, l4 + 127, l4 + 127, q40, v);
        stcs4(&ob[32], v);

        // s=2: lanes<=4 row0 (C=255), lanes>=5 row1 (C=-18); lane4 mixed.
        {
            const bool hi = lane >= 5;
            const int t0 = l4 + (hi ? -18 : 255);
            const float4 q4m = SEL4(hi, q41, q40);
            BODY(hi ? rb1 : rb0, t0, t0, q4m, v);
            if (lane == 4) { v.y = 1.0f; v.z = sm[qb1]; v.w = sm[qb1 + 1]; }
            stcs4(&ob[64], v);
        }

        // s=3: row1, C=110.
        BODY(rb1, l4 + 110, l4 + 110, q41, v);
        stcs4(&ob[96], v);

        // s=4: lanes<=8 row1 (C=238), lanes>=9 row2 (C=-35); lane8 mixed.
        {
            const bool hi = lane >= 9;
            const int t0 = l4 + (hi ? -35 : 238);
            const float4 q4m = SEL4(hi, q42, q41);
            BODY(hi ? rb2 : rb1, t0, t0, q4m, v);
            if (lane == 8) { v.z = 1.0f; v.w = q42.w; }   // q2[0] = q42.w (b0=13)
            stcs4(&ob[128], v);
        }

        // s=5: row2, C=93.
        BODY(rb2, l4 + 93, l4 + 93, q42, v);
        stcs4(&ob[160], v);

        // s=6: lanes<=12 row2 (C=221), lanes>=13 row3 (C=-52); lane12 mixed.
        {
            const bool hi = lane >= 13;
            const int t0 = l4 + (hi ? -52 : 221);
            const float4 q4m = SEL4(hi, q43, q42);
            BODY(hi ? rb3 : rb2, t0, t0, q4m, v);
            if (lane == 12) { v.w = 1.0f; }
            stcs4(&ob[192], v);
        }

        // s=7: row3, C=76.
        BODY(rb3, l4 + 76, l4 + 76, q43, v);
        stcs4(&ob[224], v);

        // s=8: row3, C=204, lanes 0..16 only.
        if (lane < 17) {
            BODY(rb3, l4 + 204, l4 + 204, q43, v);
            stcs4(&ob[256], v);
        }
#undef BODY
#undef SEL4
    } else {
        // partial tail block (not hit for the bench shape): scalar fallback
        const float s_quad = 0.17677669529663689f;
        const unsigned int iend = (unsigned int)rows * OPR;
        for (unsigned int g = (unsigned int)row0 * OPR + tid; g < iend;
             g += THREADS) {
            const unsigned int row = g / OPR;
            const int mm = (int)(g - row * OPR);
            const float* xr = x + (size_t)row * D;
            float vv;
            if (mm == 0) vv = 1.0f;
            else if (mm < 17) vv = xr[mm - 1] * 0.5f;
            else { const int k = mm - 17; vv = xr[k >> 4] * xr[k & 15] * s_quad; }
            out[g] = vv;
        }
    }
}

extern "C" void kernel_launch(void* const* d_in, const int* in_sizes, int n_in,
                              void* d_out, int out_size) {
    const float* x = (const float*)d_in[0];
    float* out = (float*)d_out;

    const int rows = in_sizes[0] / D;                            // 262144
    const int blocks = (rows + ROWS_PER_BLOCK - 1) / ROWS_PER_BLOCK; // 8192

    taylor_hqs_kernel<<<blocks, THREADS>>>(x, out, rows);
}